// round 1
// baseline (speedup 1.0000x reference)
#include <cuda_runtime.h>
#include <math.h>

// Problem constants (from reference): NUM_NODES=10000, NUM_EDGES=8192, NNZ=320000, TOP_K=5
#define NV    10000
#define NE    8192
#define MAXNZ 320000
#define TOPK  5

// Scratch (no allocations allowed -> __device__ globals)
__device__ int   g_is32;
__device__ int   g_counts[NV];
__device__ int   g_cursor[NV];
__device__ int   g_offsets[NV + 1];
__device__ int   g_bucket[MAXNZ];
__device__ float g_scores[MAXNZ];

// ---------------------------------------------------------------------------
// K0: zero counters + detect int32 vs int64 storage of edge_index.
// If edge_index is int64 (values in [0,8192)), every odd 32-bit word is 0.
// If int32, odd words are random ids; P(128 ids all zero) ~ (1/8192)^128 ~ 0.
// ---------------------------------------------------------------------------
__global__ void k_init(const void* ein) {
    int t = blockIdx.x * blockDim.x + threadIdx.x;
    int stride = gridDim.x * blockDim.x;
    for (int i = t; i < NV; i += stride) { g_counts[i] = 0; g_cursor[i] = 0; }
    if (blockIdx.x == 0 && threadIdx.x < 32) {
        const int* p = (const int*)ein;
        unsigned nz = 0;
        #pragma unroll
        for (int j = 0; j < 4; j++) {
            int w = 2 * (threadIdx.x * 4 + j) + 1;   // odd 32-bit words, first 256 words
            nz |= (unsigned)p[w];
        }
        unsigned any = __ballot_sync(0xffffffffu, nz != 0);
        if (threadIdx.x == 0) g_is32 = (any != 0) ? 1 : 0;
    }
}

__device__ __forceinline__ int read_idx(const void* p, long long i, int is32) {
    return is32 ? ((const int*)p)[i] : (int)((const long long*)p)[i];
}

// ---------------------------------------------------------------------------
// K1: gather logits, compute sigmoid scores, count per-node degree.
// ---------------------------------------------------------------------------
__global__ void k_score(const void* ein, const float* __restrict__ logits, int nnz) {
    int is32 = g_is32;
    int stride = gridDim.x * blockDim.x;
    for (int i = blockIdx.x * blockDim.x + threadIdx.x; i < nnz; i += stride) {
        int v = read_idx(ein, i, is32);
        int e = read_idx(ein, (long long)nnz + i, is32);
        float x = __ldg(&logits[(long long)v * NE + e]);
        float s = 1.0f / (1.0f + expf(-x));
        g_scores[i] = s;
        atomicAdd(&g_counts[v], 1);
    }
}

// ---------------------------------------------------------------------------
// K2: single-block exclusive scan over g_counts -> g_offsets (NV+1 entries).
// ---------------------------------------------------------------------------
__global__ void k_scan() {
    __shared__ int sh[1024];
    const int T = 1024;
    const int per = (NV + T - 1) / T;   // 10
    int tid = threadIdx.x;
    int base = tid * per;
    int sum = 0;
    for (int j = 0; j < per; j++) {
        int idx = base + j;
        if (idx < NV) sum += g_counts[idx];
    }
    sh[tid] = sum;
    __syncthreads();
    for (int off = 1; off < T; off <<= 1) {
        int vv = 0;
        if (tid >= off) vv = sh[tid - off];
        __syncthreads();
        sh[tid] += vv;
        __syncthreads();
    }
    int run = (tid == 0) ? 0 : sh[tid - 1];
    for (int j = 0; j < per; j++) {
        int idx = base + j;
        if (idx < NV) {
            g_offsets[idx] = run;
            run += g_counts[idx];
        }
    }
    if (tid == T - 1) g_offsets[NV] = run;
}

// ---------------------------------------------------------------------------
// K3: scatter incidence indices into per-node buckets (CSR).
// Order within a bucket is nondeterministic, but the top-k pass below is
// order-independent (unique composite keys), so the output is deterministic.
// ---------------------------------------------------------------------------
__global__ void k_scatter(const void* ein, int nnz) {
    int is32 = g_is32;
    int stride = gridDim.x * blockDim.x;
    for (int i = blockIdx.x * blockDim.x + threadIdx.x; i < nnz; i += stride) {
        int v = read_idx(ein, i, is32);
        int pos = g_offsets[v] + atomicAdd(&g_cursor[v], 1);
        g_bucket[pos] = i;
    }
}

// Composite key: score (positive float -> bit pattern preserves order) in the
// high 32 bits; (~index) in the low bits so lower original index wins ties.
// Matches the reference's stable lexsort((-scores, V_idx)) semantics.
__device__ __forceinline__ unsigned long long make_key(float s, int i) {
    return ((unsigned long long)__float_as_uint(s) << 32) |
           (unsigned long long)(0xFFFFFFFFu - (unsigned)i);
}

// ---------------------------------------------------------------------------
// K4: one warp per node. min(n, TOPK) rounds of warp max-reduction find the
// TOPK-th largest key L; kept iff key >= L (exact since keys are unique).
// Then write pruned edge_index (as float, -1 for dropped) and scores.
// ---------------------------------------------------------------------------
__global__ void k_topk(const void* ein, float* __restrict__ out, int nnz) {
    int wglobal = (blockIdx.x * blockDim.x + threadIdx.x) >> 5;
    int lane = threadIdx.x & 31;
    if (wglobal >= NV) return;
    int v = wglobal;
    int start = g_offsets[v];
    int n = g_offsets[v + 1] - start;
    if (n == 0) return;
    int is32 = g_is32;

    unsigned long long L = ~0ULL;
    int rounds = n < TOPK ? n : TOPK;
    for (int r = 0; r < rounds; r++) {
        unsigned long long best = 0;
        for (int j = lane; j < n; j += 32) {
            int i = g_bucket[start + j];
            unsigned long long k = make_key(g_scores[i], i);
            if (k < L && k > best) best = k;
        }
        #pragma unroll
        for (int o = 16; o; o >>= 1) {
            unsigned long long other = __shfl_down_sync(0xffffffffu, best, o);
            if (other > best) best = other;
        }
        best = __shfl_sync(0xffffffffu, best, 0);
        L = best;
    }
    // After min(n,TOPK) rounds, L = min(n,TOPK)-th largest key -> keep iff >= L.
    for (int j = lane; j < n; j += 32) {
        int i = g_bucket[start + j];
        float s = g_scores[i];
        unsigned long long k = make_key(s, i);
        bool kept = (k >= L);
        int e = read_idx(ein, (long long)nnz + i, is32);
        out[i]            = kept ? (float)v : -1.0f;
        out[nnz + i]      = kept ? (float)e : -1.0f;
        out[2 * nnz + i]  = s;
    }
}

// ---------------------------------------------------------------------------
extern "C" void kernel_launch(void* const* d_in, const int* in_sizes, int n_in,
                              void* d_out, int out_size) {
    const void*  edge_index = d_in[0];
    const float* logits     = (const float*)d_in[1];
    float*       out        = (float*)d_out;
    int nnz = in_sizes[0] / 2;          // [2, nnz]

    const int TPB = 256;
    int blocks_nnz  = (nnz + TPB - 1) / TPB;
    int blocks_topk = (NV * 32 + TPB - 1) / TPB;  // one warp per node

    k_init<<<40, TPB>>>(edge_index);
    k_score<<<blocks_nnz, TPB>>>(edge_index, logits, nnz);
    k_scan<<<1, 1024>>>();
    k_scatter<<<blocks_nnz, TPB>>>(edge_index, nnz);
    k_topk<<<blocks_topk, TPB>>>(edge_index, out, nnz);
    (void)n_in; (void)out_size;
}

// round 5
// speedup vs baseline: 1.5616x; 1.5616x over previous
#include <cuda_runtime.h>
#include <math.h>

// Problem constants: NUM_NODES=10000, NUM_EDGES=8192, NNZ=320000, TOP_K=5
#define NV    10000
#define NE    8192
#define TOPK  5

// Scratch: per-node top-5 key slots (descending), monotone under atomicMax.
__device__ unsigned long long g_top[NV * TOPK];
__device__ float g_scores[320000];
__device__ int   g_is32;

// ---------------------------------------------------------------------------
// K0: zero slot table + detect int32 vs int64 storage of edge_index.
// int64 ids < 8192 -> every odd 32-bit word is 0. int32 -> random nonzero.
// ---------------------------------------------------------------------------
__global__ void k_init(const void* ein) {
    int t = blockIdx.x * blockDim.x + threadIdx.x;
    int stride = gridDim.x * blockDim.x;
    for (int i = t; i < NV * TOPK; i += stride) g_top[i] = 0ULL;
    if (blockIdx.x == 0 && threadIdx.x < 32) {
        const int* p = (const int*)ein;
        unsigned nz = 0;
        #pragma unroll
        for (int j = 0; j < 4; j++) nz |= (unsigned)p[2 * (threadIdx.x * 4 + j) + 1];
        unsigned any = __ballot_sync(0xffffffffu, nz != 0);
        if (threadIdx.x == 0) g_is32 = (any != 0) ? 1 : 0;
    }
}

__device__ __forceinline__ int read_idx(const void* p, long long i, int is32) {
    return is32 ? ((const int*)p)[i] : (int)((const long long*)p)[i];
}

// Composite key: positive float score bits in high word (order-preserving),
// ~index low so lower original index wins ties. Always > 0, unique per i.
__device__ __forceinline__ unsigned long long make_key(float s, int i) {
    return ((unsigned long long)__float_as_uint(s) << 32) |
           (unsigned long long)(0xFFFFFFFFu - (unsigned)i);
}

// ---------------------------------------------------------------------------
// K1: gather logit, sigmoid, store score, and insert key into the node's
// top-5 via an atomicMax cascade. Final slot state is the exact top-5 set
// regardless of interleaving:
//  - slots are monotone non-decreasing,
//  - a value enters slot j+1 only after slot j holds something larger,
//  - every displaced value is carried down by exactly one thread,
//  - a value dropped past slot4 provably has >=5 larger inserted keys above.
// ---------------------------------------------------------------------------
__global__ void k_insert(const void* ein, const float* __restrict__ logits, int nnz) {
    int is32 = g_is32;
    int stride = gridDim.x * blockDim.x;
    for (int i = blockIdx.x * blockDim.x + threadIdx.x; i < nnz; i += stride) {
        int v = read_idx(ein, i, is32);
        int e = read_idx(ein, (long long)nnz + i, is32);
        float x = __ldg(&logits[(long long)v * NE + e]);
        float s = 1.0f / (1.0f + __expf(-x));
        g_scores[i] = s;

        unsigned long long k = make_key(s, i);
        unsigned long long* slots = &g_top[v * TOPK];
        // Prune: slot4 only grows; stale-smaller read is conservative.
        if (k < slots[TOPK - 1]) continue;
        #pragma unroll
        for (int j = 0; j < TOPK; j++) {
            unsigned long long cur = slots[j];
            if (cur > k) continue;                 // definitely loses here; try lower slot
            unsigned long long old = atomicMax(&slots[j], k);
            if (old < k) {                         // inserted; carry displaced value down
                k = old;
                if (k == 0ULL) break;              // displaced a sentinel: done
            }
        }
    }
}

// ---------------------------------------------------------------------------
// K2: threshold = slot4 (0 if degree < 5 -> keep all, since keys > 0).
// kept iff key >= threshold (exact: keys unique). Write pruned edge_index
// (float, -1 for dropped) and scores.
// ---------------------------------------------------------------------------
__global__ void k_output(const void* ein, float* __restrict__ out, int nnz) {
    int is32 = g_is32;
    int stride = gridDim.x * blockDim.x;
    for (int i = blockIdx.x * blockDim.x + threadIdx.x; i < nnz; i += stride) {
        int v = read_idx(ein, i, is32);
        int e = read_idx(ein, (long long)nnz + i, is32);
        float s = g_scores[i];
        unsigned long long k = make_key(s, i);
        unsigned long long L = __ldg(&g_top[v * TOPK + (TOPK - 1)]);
        bool kept = (k >= L);
        out[i]           = kept ? (float)v : -1.0f;
        out[nnz + i]     = kept ? (float)e : -1.0f;
        out[2 * nnz + i] = s;
    }
}

// ---------------------------------------------------------------------------
extern "C" void kernel_launch(void* const* d_in, const int* in_sizes, int n_in,
                              void* d_out, int out_size) {
    const void*  edge_index = d_in[0];
    const float* logits     = (const float*)d_in[1];
    float*       out        = (float*)d_out;
    int nnz = in_sizes[0] / 2;   // [2, nnz]

    const int TPB = 256;
    int blocks = (nnz + TPB - 1) / TPB;

    k_init<<<64, TPB>>>(edge_index);
    k_insert<<<blocks, TPB>>>(edge_index, logits, nnz);
    k_output<<<blocks, TPB>>>(edge_index, out, nnz);
    (void)n_in; (void)out_size;
}